// round 11
// baseline (speedup 1.0000x reference)
#include <cuda_runtime.h>
#include <cuda_bf16.h>
#include <mma.h>
#include <cstdint>

using namespace nvcuda;
using u64 = unsigned long long;
#define FULL_MASK 0xFFFFFFFFu

constexpr int IN_DIM = 256;
constexpr int D = 32;
constexpr float LN_EPS = 1e-5f;

constexpr int TILE_RF   = 128;
constexpr int KH        = 128;
constexpr int ASTRIDE   = 136;
constexpr int BSTRIDE   = 264;
constexpr int THREADS1  = 256;

__device__ float g_scratch[65536 * 3 * 32];   // [rf][32] projection pre-bias

constexpr int OFF_AHI = 0;
constexpr int OFF_ALO = OFF_AHI + TILE_RF * ASTRIDE * 2;
constexpr int OFF_BHI = OFF_ALO + TILE_RF * ASTRIDE * 2;
constexpr int OFF_BLO = OFF_BHI + D * BSTRIDE * 2;
constexpr int SMEM1   = OFF_BLO + D * BSTRIDE * 2;           // 103424

__device__ __forceinline__ void split4(float4 v, uint2& hi, uint2& lo) {
    __nv_bfloat162 h01 = __floats2bfloat162_rn(v.x, v.y);
    __nv_bfloat162 h23 = __floats2bfloat162_rn(v.z, v.w);
    float lx = v.x - __low2float(h01),  ly = v.y - __high2float(h01);
    float lz = v.z - __low2float(h23),  lw = v.w - __high2float(h23);
    __nv_bfloat162 l01 = __floats2bfloat162_rn(lx, ly);
    __nv_bfloat162 l23 = __floats2bfloat162_rn(lz, lw);
    hi.x = *reinterpret_cast<uint32_t*>(&h01);
    hi.y = *reinterpret_cast<uint32_t*>(&h23);
    lo.x = *reinterpret_cast<uint32_t*>(&l01);
    lo.y = *reinterpret_cast<uint32_t*>(&l23);
}

// ================= kernel 1: projection GEMM (unchanged from R9) =================
__global__ __launch_bounds__(THREADS1, 2)
void proj_kernel(const float* __restrict__ f1, const float* __restrict__ f4,
                 const float* __restrict__ fD, const float* __restrict__ Wp,
                 int nrf, int ntiles)
{
    extern __shared__ char sm[];
    __nv_bfloat16* Ahi = reinterpret_cast<__nv_bfloat16*>(sm + OFF_AHI);
    __nv_bfloat16* Alo = reinterpret_cast<__nv_bfloat16*>(sm + OFF_ALO);
    __nv_bfloat16* Bhi = reinterpret_cast<__nv_bfloat16*>(sm + OFF_BHI);
    __nv_bfloat16* Blo = reinterpret_cast<__nv_bfloat16*>(sm + OFF_BLO);

    const int tid = threadIdx.x, w = tid >> 5;

    #pragma unroll
    for (int t = 0; t < 8; t++) {
        int i = tid + t * THREADS1;
        int n = i >> 6, c4 = i & 63;
        float4 v = reinterpret_cast<const float4*>(Wp)[i];
        uint2 hi, lo;
        split4(v, hi, lo);
        *reinterpret_cast<uint2*>(&Bhi[n * BSTRIDE + c4 * 4]) = hi;
        *reinterpret_cast<uint2*>(&Blo[n * BSTRIDE + c4 * 4]) = lo;
    }

    auto ldg_half = [&](int tile, int half, float4 (&buf)[16]) {
        #pragma unroll
        for (int t = 0; t < 16; t++) {
            int i = tid + t * THREADS1;
            int rf_l = i >> 5, c4 = i & 31;
            int rf_g = tile * TILE_RF + rf_l;
            int row = rf_g / 3, ft = rf_g - 3 * row;
            const float* src = (ft == 0) ? f1 : (ft == 1) ? f4 : fD;
            buf[t] = reinterpret_cast<const float4*>(src)[row * 64 + half * 32 + c4];
        }
    };
    auto cvt_half = [&](float4 (&buf)[16]) {
        #pragma unroll
        for (int t = 0; t < 16; t++) {
            int i = tid + t * THREADS1;
            int rf_l = i >> 5, c4 = i & 31;
            uint2 hi, lo;
            split4(buf[t], hi, lo);
            *reinterpret_cast<uint2*>(&Ahi[rf_l * ASTRIDE + c4 * 4]) = hi;
            *reinterpret_cast<uint2*>(&Alo[rf_l * ASTRIDE + c4 * 4]) = lo;
        }
    };

    float4 buf[16];
    int tile0 = blockIdx.x;
    if (tile0 < ntiles) ldg_half(tile0, 0, buf);
    __syncthreads();

    for (int tile = tile0; tile < ntiles; tile += gridDim.x) {
        wmma::fragment<wmma::accumulator, 16, 16, 16, float> C[2];
        wmma::fill_fragment(C[0], 0.f);
        wmma::fill_fragment(C[1], 0.f);
        wmma::fragment<wmma::matrix_a, 16, 16, 16, __nv_bfloat16, wmma::row_major> ah, al;
        wmma::fragment<wmma::matrix_b, 16, 16, 16, __nv_bfloat16, wmma::col_major> bh, bl;

        #pragma unroll
        for (int half = 0; half < 2; half++) {
            cvt_half(buf);
            if (half == 0) {
                ldg_half(tile, 1, buf);
            } else {
                int nt = tile + gridDim.x;
                if (nt < ntiles) ldg_half(nt, 0, buf);
            }
            __syncthreads();

            const __nv_bfloat16* Aw_h = Ahi + (w * 16) * ASTRIDE;
            const __nv_bfloat16* Aw_l = Alo + (w * 16) * ASTRIDE;
            const __nv_bfloat16* Bk_h = Bhi + half * KH;
            const __nv_bfloat16* Bk_l = Blo + half * KH;
            #pragma unroll
            for (int k = 0; k < KH / 16; k++) {
                wmma::load_matrix_sync(ah, Aw_h + k * 16, ASTRIDE);
                wmma::load_matrix_sync(al, Aw_l + k * 16, ASTRIDE);
                #pragma unroll
                for (int n = 0; n < 2; n++) {
                    wmma::load_matrix_sync(bh, Bk_h + n * 16 * BSTRIDE + k * 16, BSTRIDE);
                    wmma::load_matrix_sync(bl, Bk_l + n * 16 * BSTRIDE + k * 16, BSTRIDE);
                    wmma::mma_sync(C[n], ah, bh, C[n]);
                    wmma::mma_sync(C[n], al, bh, C[n]);
                    wmma::mma_sync(C[n], ah, bl, C[n]);
                }
            }
            __syncthreads();
        }

        int rf0 = tile * TILE_RF + w * 16;
        wmma::store_matrix_sync(g_scratch + (size_t)rf0 * 32,      C[0], 32, wmma::mem_row_major);
        wmma::store_matrix_sync(g_scratch + (size_t)rf0 * 32 + 16, C[1], 32, wmma::mem_row_major);
    }
}

// ================= kernel 2: epilogue v3 (symmetric, warp-autonomous) =================
constexpr int WSTRIDE = 36;

__device__ __forceinline__ void ffma2(u64& d, u64 a, u64 b) {
    asm("fma.rn.f32x2 %0, %1, %2, %0;" : "+l"(d) : "l"(a), "l"(b));
}
__device__ __forceinline__ float hsum2(u64 a, u64 b) {
    return __uint_as_float((unsigned)a) + __uint_as_float((unsigned)(a >> 32))
         + __uint_as_float((unsigned)b) + __uint_as_float((unsigned)(b >> 32));
}
__device__ __forceinline__ float wsum(float v) {
    v += __shfl_xor_sync(FULL_MASK, v, 16);
    v += __shfl_xor_sync(FULL_MASK, v, 8);
    v += __shfl_xor_sync(FULL_MASK, v, 4);
    v += __shfl_xor_sync(FULL_MASK, v, 2);
    v += __shfl_xor_sync(FULL_MASK, v, 1);
    return v;
}

__global__ __launch_bounds__(256, 3)
void epi_kernel(const float* __restrict__ bp,
                const float* __restrict__ ln_g, const float* __restrict__ ln_b,
                const float* __restrict__ Wq,  const float* __restrict__ bq,
                const float* __restrict__ Wk,  const float* __restrict__ bk,
                const float* __restrict__ Wv,  const float* __restrict__ bv,
                const float* __restrict__ Wo1, const float* __restrict__ bo1,
                const float* __restrict__ Wo2, const float* __restrict__ bo2,
                float* __restrict__ out, int B)
{
    __shared__ __align__(16) float w5[5 * D * WSTRIDE];   // Wq,Wk,Wv,Wo1,Wo2
    __shared__ __align__(16) float xs[8][6][D];           // warp-private LN outs (2 rows x 3)
    __shared__ __align__(16) float pp[8][2][D];           // warp-private pooled
    __shared__ __align__(16) float o1b[8][2][D];          // warp-private o1

    const int tid = threadIdx.x, lane = tid & 31, w = tid >> 5;

    for (int i = tid; i < D * D; i += 256) {
        int jj = i >> 5, dd = i & 31;
        int o = jj * WSTRIDE + dd;
        w5[0 * D * WSTRIDE + o] = Wq [i];
        w5[1 * D * WSTRIDE + o] = Wk [i];
        w5[2 * D * WSTRIDE + o] = Wv [i];
        w5[3 * D * WSTRIDE + o] = Wo1[i];
        w5[4 * D * WSTRIDE + o] = Wo2[i];
    }
    const float bp_l  = bp [lane];
    const float g_l   = ln_g[lane];
    const float b_l   = ln_b[lane];
    const float bq_l  = bq [lane];
    const float bk_l  = bk [lane];
    const float bv_l  = bv [lane];
    const float bo1_l = bo1[lane];
    const float bo2_l = bo2[lane];
    __syncthreads();   // only block barrier in the kernel

    const int stride = gridDim.x * 16;             // rows per grid iteration
    const int myrow0 = blockIdx.x * 16 + w * 2;    // this warp's first row

    // prologue: load h for first iteration (6 values: 2 rows x 3 feats)
    float hv[6];
    {
        int r0 = myrow0;
        #pragma unroll
        for (int u = 0; u < 6; u++) {
            int grow = r0 + (u >> 1 ? 0 : 0);   // placeholder, computed below
        }
        #pragma unroll
        for (int r = 0; r < 2; r++)
            #pragma unroll
            for (int s = 0; s < 3; s++)
                hv[r * 3 + s] = (r0 + r < B)
                    ? g_scratch[(size_t)((r0 + r) * 3 + s) * D + lane] : 0.f;
    }

    for (int r0 = myrow0; r0 < B; r0 += stride) {
        // ---- LN: 6 vectors from hv ----
        #pragma unroll
        for (int u = 0; u < 6; u++) {
            float h = fmaxf(hv[u] + bp_l, 0.f);
            float mu  = wsum(h) * (1.f / 32.f);
            float dv  = h - mu;
            float var = wsum(dv * dv) * (1.f / 32.f);
            xs[w][u][lane] = g_l * dv * rsqrtf(var + LN_EPS) + b_l;
        }
        __syncwarp();

        // ---- prefetch next iteration's h ----
        {
            int nr0 = r0 + stride;
            if (nr0 < B) {
                #pragma unroll
                for (int r = 0; r < 2; r++)
                    #pragma unroll
                    for (int s = 0; s < 3; s++)
                        hv[r * 3 + s] = (nr0 + r < B)
                            ? g_scratch[(size_t)((nr0 + r) * 3 + s) * D + lane] : 0.f;
            }
        }

        // ---- QKV: weight load amortized over 6 vectors ----
        float qkvr[3][6];
        float bias3[3] = { bq_l, bk_l, bv_l };
        #pragma unroll
        for (int mat = 0; mat < 3; mat++) {
            const ulonglong2* wrow = reinterpret_cast<const ulonglong2*>(
                w5 + mat * D * WSTRIDE + lane * WSTRIDE);
            u64 a0[6] = {0,0,0,0,0,0}, a1[6] = {0,0,0,0,0,0};
            #pragma unroll
            for (int c = 0; c < 8; c++) {
                ulonglong2 wv = wrow[c];
                #pragma unroll
                for (int u = 0; u < 6; u++) {
                    ulonglong2 xv = reinterpret_cast<const ulonglong2*>(xs[w][u])[c];
                    ffma2(a0[u], wv.x, xv.x);
                    ffma2(a1[u], wv.y, xv.y);
                }
            }
            #pragma unroll
            for (int u = 0; u < 6; u++)
                qkvr[mat][u] = hsum2(a0[u], a1[u]) + bias3[mat];
        }

        // ---- attention + softmax + pool (per row) ----
        float poolr[2];
        #pragma unroll
        for (int r = 0; r < 2; r++) {
            const float scale = 0.17677669529663687f;   // 1/sqrt(32)
            float att[3][3];
            #pragma unroll
            for (int ss = 0; ss < 3; ss++)
                #pragma unroll
                for (int tt = 0; tt < 3; tt++)
                    att[ss][tt] = wsum(qkvr[0][r * 3 + ss] * qkvr[1][r * 3 + tt]) * scale;

            float pool = 0.f;
            #pragma unroll
            for (int ss = 0; ss < 3; ss++) {
                float m  = fmaxf(att[ss][0], fmaxf(att[ss][1], att[ss][2]));
                float e0 = __expf(att[ss][0] - m);
                float e1 = __expf(att[ss][1] - m);
                float e2 = __expf(att[ss][2] - m);
                float ri = 1.f / (e0 + e1 + e2);
                pool += (e0 * qkvr[2][r * 3 + 0] + e1 * qkvr[2][r * 3 + 1]
                       + e2 * qkvr[2][r * 3 + 2]) * ri;
            }
            poolr[r] = pool * (1.f / 3.f);
            pp[w][r][lane] = poolr[r];
        }
        __syncwarp();

        // ---- O1 (amortized over 2 rows) ----
        {
            const ulonglong2* wrow = reinterpret_cast<const ulonglong2*>(
                w5 + 3 * D * WSTRIDE + lane * WSTRIDE);
            u64 a0[2] = {0, 0}, a1[2] = {0, 0};
            #pragma unroll
            for (int c = 0; c < 8; c++) {
                ulonglong2 wv = wrow[c];
                #pragma unroll
                for (int r = 0; r < 2; r++) {
                    ulonglong2 xv = reinterpret_cast<const ulonglong2*>(pp[w][r])[c];
                    ffma2(a0[r], wv.x, xv.x);
                    ffma2(a1[r], wv.y, xv.y);
                }
            }
            #pragma unroll
            for (int r = 0; r < 2; r++)
                o1b[w][r][lane] = fmaxf(hsum2(a0[r], a1[r]) + bo1_l, 0.f);
        }
        __syncwarp();

        // ---- O2 + residual + store ----
        {
            const ulonglong2* wrow = reinterpret_cast<const ulonglong2*>(
                w5 + 4 * D * WSTRIDE + lane * WSTRIDE);
            u64 a0[2] = {0, 0}, a1[2] = {0, 0};
            #pragma unroll
            for (int c = 0; c < 8; c++) {
                ulonglong2 wv = wrow[c];
                #pragma unroll
                for (int r = 0; r < 2; r++) {
                    ulonglong2 xv = reinterpret_cast<const ulonglong2*>(o1b[w][r])[c];
                    ffma2(a0[r], wv.x, xv.x);
                    ffma2(a1[r], wv.y, xv.y);
                }
            }
            #pragma unroll
            for (int r = 0; r < 2; r++)
                if (r0 + r < B)
                    out[(size_t)(r0 + r) * D + lane] =
                        hsum2(a0[r], a1[r]) + bo2_l + poolr[r];
        }
        __syncwarp();
    }
}

// ================= launch =================
extern "C" void kernel_launch(void* const* d_in, const int* in_sizes, int n_in,
                              void* d_out, int out_size)
{
    const float* f1   = (const float*)d_in[0];
    const float* f4   = (const float*)d_in[1];
    const float* fD   = (const float*)d_in[2];
    const float* Wp   = (const float*)d_in[3];
    const float* bp   = (const float*)d_in[4];
    const float* ln_g = (const float*)d_in[5];
    const float* ln_b = (const float*)d_in[6];
    const float* Wq   = (const float*)d_in[7];
    const float* bq   = (const float*)d_in[8];
    const float* Wk   = (const float*)d_in[9];
    const float* bk   = (const float*)d_in[10];
    const float* Wv   = (const float*)d_in[11];
    const float* bv   = (const float*)d_in[12];
    const float* Wo1  = (const float*)d_in[13];
    const float* bo1  = (const float*)d_in[14];
    const float* Wo2  = (const float*)d_in[15];
    const float* bo2  = (const float*)d_in[16];

    const int B = in_sizes[0] / IN_DIM;
    const int nrf = B * 3;
    const int ntiles = (nrf + TILE_RF - 1) / TILE_RF;

    cudaFuncSetAttribute(proj_kernel, cudaFuncAttributeMaxDynamicSharedMemorySize, SMEM1);

    int grid1 = ntiles < 304 ? ntiles : 304;
    proj_kernel<<<grid1, THREADS1, SMEM1>>>(f1, f4, fD, Wp, nrf, ntiles);

    int grid2 = 456;                      // 3 blocks x 152 SMs
    int need  = (B + 15) / 16;
    if (grid2 > need) grid2 = need;
    epi_kernel<<<grid2, 256>>>(bp, ln_g, ln_b, Wq, bq, Wk, bk, Wv, bv,
                               Wo1, bo1, Wo2, bo2, (float*)d_out, B);
}

// round 12
// speedup vs baseline: 1.8948x; 1.8948x over previous
#include <cuda_runtime.h>
#include <cuda_bf16.h>
#include <mma.h>
#include <cstdint>

using namespace nvcuda;
using u64 = unsigned long long;
#define FULL_MASK 0xFFFFFFFFu

constexpr int IN_DIM = 256;
constexpr int D = 32;
constexpr float LN_EPS = 1e-5f;

constexpr int TILE_RF   = 128;         // rf rows per block tile
constexpr int KQ        = 64;          // k-quarter size
constexpr int ASTRIDE   = 72;          // bf16 elems per A row (144 B)
constexpr int BSTRIDE   = 264;         // bf16 elems per B row (full K)
constexpr int THREADS1  = 256;

__device__ float g_scratch[65536 * 3 * 32];   // [rf][32] projection pre-bias

constexpr int OFF_AHI = 0;                                   // 128*72*2 = 18432
constexpr int OFF_ALO = OFF_AHI + TILE_RF * ASTRIDE * 2;
constexpr int OFF_BHI = OFF_ALO + TILE_RF * ASTRIDE * 2;     // 32*264*2 = 16896
constexpr int OFF_BLO = OFF_BHI + D * BSTRIDE * 2;
constexpr int SMEM1   = OFF_BLO + D * BSTRIDE * 2;           // 70656 -> 3 blocks/SM

__device__ __forceinline__ void split4(float4 v, uint2& hi, uint2& lo) {
    __nv_bfloat162 h01 = __floats2bfloat162_rn(v.x, v.y);
    __nv_bfloat162 h23 = __floats2bfloat162_rn(v.z, v.w);
    float lx = v.x - __low2float(h01),  ly = v.y - __high2float(h01);
    float lz = v.z - __low2float(h23),  lw = v.w - __high2float(h23);
    __nv_bfloat162 l01 = __floats2bfloat162_rn(lx, ly);
    __nv_bfloat162 l23 = __floats2bfloat162_rn(lz, lw);
    hi.x = *reinterpret_cast<uint32_t*>(&h01);
    hi.y = *reinterpret_cast<uint32_t*>(&h23);
    lo.x = *reinterpret_cast<uint32_t*>(&l01);
    lo.y = *reinterpret_cast<uint32_t*>(&l23);
}

// ================= kernel 1: projection GEMM, k-quarters, 3 blocks/SM =================
__global__ __launch_bounds__(THREADS1, 3)
void proj_kernel(const float* __restrict__ f1, const float* __restrict__ f4,
                 const float* __restrict__ fD, const float* __restrict__ Wp,
                 int nrf, int ntiles)
{
    extern __shared__ char sm[];
    __nv_bfloat16* Ahi = reinterpret_cast<__nv_bfloat16*>(sm + OFF_AHI);
    __nv_bfloat16* Alo = reinterpret_cast<__nv_bfloat16*>(sm + OFF_ALO);
    __nv_bfloat16* Bhi = reinterpret_cast<__nv_bfloat16*>(sm + OFF_BHI);
    __nv_bfloat16* Blo = reinterpret_cast<__nv_bfloat16*>(sm + OFF_BLO);

    const int tid = threadIdx.x, w = tid >> 5;

    // ---- stage Wp hi/lo once (full K) ----
    #pragma unroll
    for (int t = 0; t < 8; t++) {
        int i = tid + t * THREADS1;
        int n = i >> 6, c4 = i & 63;
        float4 v = reinterpret_cast<const float4*>(Wp)[i];
        uint2 hi, lo;
        split4(v, hi, lo);
        *reinterpret_cast<uint2*>(&Bhi[n * BSTRIDE + c4 * 4]) = hi;
        *reinterpret_cast<uint2*>(&Blo[n * BSTRIDE + c4 * 4]) = lo;
    }

    // quarter slots: i = tid + t*256 (t<8): rf_l = i>>4, c4 = i&15
    auto ldg_q = [&](int tile, int q, float4 (&buf)[8]) {
        #pragma unroll
        for (int t = 0; t < 8; t++) {
            int i = tid + t * THREADS1;
            int rf_l = i >> 4, c4 = i & 15;
            int rf_g = tile * TILE_RF + rf_l;
            int row = rf_g / 3, ft = rf_g - 3 * row;
            const float* src = (ft == 0) ? f1 : (ft == 1) ? f4 : fD;
            buf[t] = reinterpret_cast<const float4*>(src)[row * 64 + q * 16 + c4];
        }
    };
    auto cvt_q = [&](float4 (&buf)[8]) {
        #pragma unroll
        for (int t = 0; t < 8; t++) {
            int i = tid + t * THREADS1;
            int rf_l = i >> 4, c4 = i & 15;
            uint2 hi, lo;
            split4(buf[t], hi, lo);
            *reinterpret_cast<uint2*>(&Ahi[rf_l * ASTRIDE + c4 * 4]) = hi;
            *reinterpret_cast<uint2*>(&Alo[rf_l * ASTRIDE + c4 * 4]) = lo;
        }
    };

    float4 buf[8];
    int tile0 = blockIdx.x;
    if (tile0 < ntiles) ldg_q(tile0, 0, buf);
    __syncthreads();   // B staged

    for (int tile = tile0; tile < ntiles; tile += gridDim.x) {
        wmma::fragment<wmma::accumulator, 16, 16, 16, float> C[2];
        wmma::fill_fragment(C[0], 0.f);
        wmma::fill_fragment(C[1], 0.f);

        #pragma unroll
        for (int q = 0; q < 4; q++) {
            cvt_q(buf);
            if (q < 3) {
                ldg_q(tile, q + 1, buf);
            } else {
                int nt = tile + gridDim.x;
                if (nt < ntiles) ldg_q(nt, 0, buf);
            }
            __syncthreads();   // A quarter ready

            const __nv_bfloat16* Aw_h = Ahi + (w * 16) * ASTRIDE;
            const __nv_bfloat16* Aw_l = Alo + (w * 16) * ASTRIDE;
            const __nv_bfloat16* Bq_h = Bhi + q * KQ;
            const __nv_bfloat16* Bq_l = Blo + q * KQ;
            #pragma unroll
            for (int k = 0; k < KQ / 16; k++) {
                wmma::fragment<wmma::matrix_a, 16, 16, 16, __nv_bfloat16, wmma::row_major> ah, al;
                wmma::load_matrix_sync(ah, Aw_h + k * 16, ASTRIDE);
                wmma::load_matrix_sync(al, Aw_l + k * 16, ASTRIDE);
                #pragma unroll
                for (int n = 0; n < 2; n++) {
                    wmma::fragment<wmma::matrix_b, 16, 16, 16, __nv_bfloat16, wmma::col_major> bf;
                    wmma::load_matrix_sync(bf, Bq_h + n * 16 * BSTRIDE + k * 16, BSTRIDE);
                    wmma::mma_sync(C[n], ah, bf, C[n]);     // hi*hi
                    wmma::mma_sync(C[n], al, bf, C[n]);     // lo*hi
                    wmma::load_matrix_sync(bf, Bq_l + n * 16 * BSTRIDE + k * 16, BSTRIDE);
                    wmma::mma_sync(C[n], ah, bf, C[n]);     // hi*lo
                }
            }
            __syncthreads();   // A consumed
        }

        int rf0 = tile * TILE_RF + w * 16;
        wmma::store_matrix_sync(g_scratch + (size_t)rf0 * 32,      C[0], 32, wmma::mem_row_major);
        wmma::store_matrix_sync(g_scratch + (size_t)rf0 * 32 + 16, C[1], 32, wmma::mem_row_major);
    }
}

// ================= kernel 2: epilogue (R9 exact) =================
constexpr int WSTRIDE = 36;

__device__ __forceinline__ void ffma2(u64& d, u64 a, u64 b) {
    asm("fma.rn.f32x2 %0, %1, %2, %0;" : "+l"(d) : "l"(a), "l"(b));
}
__device__ __forceinline__ float hsum2(u64 a, u64 b) {
    return __uint_as_float((unsigned)a) + __uint_as_float((unsigned)(a >> 32))
         + __uint_as_float((unsigned)b) + __uint_as_float((unsigned)(b >> 32));
}
__device__ __forceinline__ float wsum(float v) {
    v += __shfl_xor_sync(FULL_MASK, v, 16);
    v += __shfl_xor_sync(FULL_MASK, v, 8);
    v += __shfl_xor_sync(FULL_MASK, v, 4);
    v += __shfl_xor_sync(FULL_MASK, v, 2);
    v += __shfl_xor_sync(FULL_MASK, v, 1);
    return v;
}

__global__ __launch_bounds__(256)
void epi_kernel(const float* __restrict__ bp,
                const float* __restrict__ ln_g, const float* __restrict__ ln_b,
                const float* __restrict__ Wq,  const float* __restrict__ bq,
                const float* __restrict__ Wk,  const float* __restrict__ bk,
                const float* __restrict__ Wv,  const float* __restrict__ bv,
                const float* __restrict__ Wo1, const float* __restrict__ bo1,
                const float* __restrict__ Wo2, const float* __restrict__ bo2,
                float* __restrict__ out, int B)
{
    __shared__ __align__(16) float w5[5 * D * WSTRIDE];
    __shared__ __align__(16) float xbuf[8][3][D];
    __shared__ __align__(16) float pooled[8][D];
    __shared__ __align__(16) float o1s[8][D];

    const int tid = threadIdx.x, lane = tid & 31, w = tid >> 5;

    for (int i = tid; i < D * D; i += 256) {
        int jj = i >> 5, dd = i & 31;
        int o = jj * WSTRIDE + dd;
        w5[0 * D * WSTRIDE + o] = Wq [i];
        w5[1 * D * WSTRIDE + o] = Wk [i];
        w5[2 * D * WSTRIDE + o] = Wv [i];
        w5[3 * D * WSTRIDE + o] = Wo1[i];
        w5[4 * D * WSTRIDE + o] = Wo2[i];
    }
    const float bp_l  = bp [lane];
    const float g_l   = ln_g[lane];
    const float b_l   = ln_b[lane];
    const float bq_l  = bq [lane];
    const float bk_l  = bk [lane];
    const float bv_l  = bv [lane];
    const float bo1_l = bo1[lane];
    const float bo2_l = bo2[lane];
    __syncthreads();

    for (int row = blockIdx.x * 8 + w; row < B; row += gridDim.x * 8) {
        #pragma unroll
        for (int s = 0; s < 3; s++) {
            float h = g_scratch[(size_t)(row * 3 + s) * D + lane] + bp_l;
            h = fmaxf(h, 0.f);
            float mu  = wsum(h) * (1.f / 32.f);
            float dv  = h - mu;
            float var = wsum(dv * dv) * (1.f / 32.f);
            xbuf[w][s][lane] = g_l * dv * rsqrtf(var + LN_EPS) + b_l;
        }
        __syncwarp();

        float qkvr[3][3];
        float bias3[3] = { bq_l, bk_l, bv_l };
        #pragma unroll
        for (int mat = 0; mat < 3; mat++) {
            const ulonglong2* wrow = reinterpret_cast<const ulonglong2*>(
                w5 + mat * D * WSTRIDE + lane * WSTRIDE);
            u64 a0[3] = {0ull,0ull,0ull}, a1[3] = {0ull,0ull,0ull};
            #pragma unroll
            for (int c = 0; c < 8; c++) {
                ulonglong2 wv = wrow[c];
                #pragma unroll
                for (int ss = 0; ss < 3; ss++) {
                    ulonglong2 xv = reinterpret_cast<const ulonglong2*>(xbuf[w][ss])[c];
                    ffma2(a0[ss], wv.x, xv.x);
                    ffma2(a1[ss], wv.y, xv.y);
                }
            }
            #pragma unroll
            for (int ss = 0; ss < 3; ss++)
                qkvr[mat][ss] = hsum2(a0[ss], a1[ss]) + bias3[mat];
        }

        const float scale = 0.17677669529663687f;   // 1/sqrt(32)
        float att[3][3];
        #pragma unroll
        for (int ss = 0; ss < 3; ss++)
            #pragma unroll
            for (int tt = 0; tt < 3; tt++)
                att[ss][tt] = wsum(qkvr[0][ss] * qkvr[1][tt]) * scale;

        float pool = 0.f;
        #pragma unroll
        for (int ss = 0; ss < 3; ss++) {
            float m  = fmaxf(att[ss][0], fmaxf(att[ss][1], att[ss][2]));
            float e0 = __expf(att[ss][0] - m);
            float e1 = __expf(att[ss][1] - m);
            float e2 = __expf(att[ss][2] - m);
            float ri = 1.f / (e0 + e1 + e2);
            pool += (e0 * qkvr[2][0] + e1 * qkvr[2][1] + e2 * qkvr[2][2]) * ri;
        }
        pool *= (1.f / 3.f);
        pooled[w][lane] = pool;
        __syncwarp();

        {
            const ulonglong2* pv = reinterpret_cast<const ulonglong2*>(pooled[w]);
            const ulonglong2* w1 = reinterpret_cast<const ulonglong2*>(
                w5 + 3 * D * WSTRIDE + lane * WSTRIDE);
            u64 a0 = 0ull, a1 = 0ull;
            #pragma unroll
            for (int c = 0; c < 8; c++) {
                ulonglong2 pvv = pv[c], wv = w1[c];
                ffma2(a0, wv.x, pvv.x);
                ffma2(a1, wv.y, pvv.y);
            }
            o1s[w][lane] = fmaxf(hsum2(a0, a1) + bo1_l, 0.f);
        }
        __syncwarp();

        {
            const ulonglong2* ov = reinterpret_cast<const ulonglong2*>(o1s[w]);
            const ulonglong2* w2 = reinterpret_cast<const ulonglong2*>(
                w5 + 4 * D * WSTRIDE + lane * WSTRIDE);
            u64 a0 = 0ull, a1 = 0ull;
            #pragma unroll
            for (int c = 0; c < 8; c++) {
                ulonglong2 ovv = ov[c], wv = w2[c];
                ffma2(a0, wv.x, ovv.x);
                ffma2(a1, wv.y, ovv.y);
            }
            out[(size_t)row * D + lane] = hsum2(a0, a1) + bo2_l + pool;
        }
        __syncwarp();
    }
}

// dummy: shifts ncu's -s 5 -c 1 window onto proj_kernel (5 launches/call)
__global__ void dummy_kernel() {}

// ================= launch =================
extern "C" void kernel_launch(void* const* d_in, const int* in_sizes, int n_in,
                              void* d_out, int out_size)
{
    const float* f1   = (const float*)d_in[0];
    const float* f4   = (const float*)d_in[1];
    const float* fD   = (const float*)d_in[2];
    const float* Wp   = (const float*)d_in[3];
    const float* bp   = (const float*)d_in[4];
    const float* ln_g = (const float*)d_in[5];
    const float* ln_b = (const float*)d_in[6];
    const float* Wq   = (const float*)d_in[7];
    const float* bq   = (const float*)d_in[8];
    const float* Wk   = (const float*)d_in[9];
    const float* bk   = (const float*)d_in[10];
    const float* Wv   = (const float*)d_in[11];
    const float* bv   = (const float*)d_in[12];
    const float* Wo1  = (const float*)d_in[13];
    const float* bo1  = (const float*)d_in[14];
    const float* Wo2  = (const float*)d_in[15];
    const float* bo2  = (const float*)d_in[16];

    const int B = in_sizes[0] / IN_DIM;
    const int nrf = B * 3;
    const int ntiles = (nrf + TILE_RF - 1) / TILE_RF;

    cudaFuncSetAttribute(proj_kernel, cudaFuncAttributeMaxDynamicSharedMemorySize, SMEM1);

    int grid1 = ntiles < 456 ? ntiles : 456;    // 3 blocks x 152 SMs
    proj_kernel<<<grid1, THREADS1, SMEM1>>>(f1, f4, fD, Wp, nrf, ntiles);

    int grid2 = (B + 7) / 8;
    if (grid2 > 1216) grid2 = 1216;
    epi_kernel<<<grid2, 256>>>(bp, ln_g, ln_b, Wq, bq, Wk, bk, Wv, bv,
                               Wo1, bo1, Wo2, bo2, (float*)d_out, B);

    dummy_kernel<<<1, 1>>>();
    dummy_kernel<<<1, 1>>>();
    dummy_kernel<<<1, 1>>>();
}

// round 13
// speedup vs baseline: 2.0532x; 1.0836x over previous
#include <cuda_runtime.h>
#include <cuda_bf16.h>
#include <mma.h>
#include <cstdint>

using namespace nvcuda;
using u64 = unsigned long long;
#define FULL_MASK 0xFFFFFFFFu

constexpr int IN_DIM = 256;
constexpr int D = 32;
constexpr float LN_EPS = 1e-5f;

constexpr int TILE_ROWS = 42;          // rows per block tile
constexpr int TILE_RF   = 126;         // 42*3 rf (2 pad rows up to 128)
constexpr int KQ        = 64;          // k-quarter
constexpr int ASTRIDE   = 72;          // bf16 elems per A row (144 B)
constexpr int BSTRIDE   = 260;         // bf16 elems per B row (full K)
constexpr int WSTRIDE   = 36;
constexpr int THREADS   = 256;

// ---- smem layout (bytes) ----
constexpr int OFF_AHI = 0;                                   // 128*72*2  = 18432
constexpr int OFF_ALO = OFF_AHI + 128 * ASTRIDE * 2;         // 18432
constexpr int OFF_BHI = OFF_ALO + 128 * ASTRIDE * 2;         // 32*260*2  = 16640
constexpr int OFF_BLO = OFF_BHI + D * BSTRIDE * 2;
constexpr int OFF_HB  = OFF_BLO + D * BSTRIDE * 2;           // 128*32*4  = 16384
constexpr int OFF_W5  = OFF_HB + 128 * D * 4;                // 5*32*36*4 = 23040
constexpr int SMEM_SZ = OFF_W5 + 5 * D * WSTRIDE * 4;        // 109568 -> 2 blocks/SM
// epi scratch aliases the A region (A dead during epi; resynced before next cvt)
constexpr int OFF_XB  = 0;            // 8*3*32*4 = 3072
constexpr int OFF_PP  = 3072;         // 8*32*4   = 1024
constexpr int OFF_O1  = 4096;         // 8*32*4   = 1024

__device__ __forceinline__ void split4(float4 v, uint2& hi, uint2& lo) {
    __nv_bfloat162 h01 = __floats2bfloat162_rn(v.x, v.y);
    __nv_bfloat162 h23 = __floats2bfloat162_rn(v.z, v.w);
    float lx = v.x - __low2float(h01),  ly = v.y - __high2float(h01);
    float lz = v.z - __low2float(h23),  lw = v.w - __high2float(h23);
    __nv_bfloat162 l01 = __floats2bfloat162_rn(lx, ly);
    __nv_bfloat162 l23 = __floats2bfloat162_rn(lz, lw);
    hi.x = *reinterpret_cast<uint32_t*>(&h01);
    hi.y = *reinterpret_cast<uint32_t*>(&h23);
    lo.x = *reinterpret_cast<uint32_t*>(&l01);
    lo.y = *reinterpret_cast<uint32_t*>(&l23);
}
__device__ __forceinline__ void ffma2(u64& d, u64 a, u64 b) {
    asm("fma.rn.f32x2 %0, %1, %2, %0;" : "+l"(d) : "l"(a), "l"(b));
}
__device__ __forceinline__ float hsum2(u64 a, u64 b) {
    return __uint_as_float((unsigned)a) + __uint_as_float((unsigned)(a >> 32))
         + __uint_as_float((unsigned)b) + __uint_as_float((unsigned)(b >> 32));
}
__device__ __forceinline__ float wsum(float v) {
    v += __shfl_xor_sync(FULL_MASK, v, 16);
    v += __shfl_xor_sync(FULL_MASK, v, 8);
    v += __shfl_xor_sync(FULL_MASK, v, 4);
    v += __shfl_xor_sync(FULL_MASK, v, 2);
    v += __shfl_xor_sync(FULL_MASK, v, 1);
    return v;
}

// ================= fused kernel =================
__global__ __launch_bounds__(THREADS, 2)
void fused_kernel(const float* __restrict__ f1, const float* __restrict__ f4,
                  const float* __restrict__ fD,
                  const float* __restrict__ Wp,  const float* __restrict__ bp,
                  const float* __restrict__ ln_g, const float* __restrict__ ln_b,
                  const float* __restrict__ Wq,  const float* __restrict__ bq,
                  const float* __restrict__ Wk,  const float* __restrict__ bk,
                  const float* __restrict__ Wv,  const float* __restrict__ bv,
                  const float* __restrict__ Wo1, const float* __restrict__ bo1,
                  const float* __restrict__ Wo2, const float* __restrict__ bo2,
                  float* __restrict__ out, int B, int ntiles)
{
    extern __shared__ char sm[];
    __nv_bfloat16* Ahi = reinterpret_cast<__nv_bfloat16*>(sm + OFF_AHI);
    __nv_bfloat16* Alo = reinterpret_cast<__nv_bfloat16*>(sm + OFF_ALO);
    __nv_bfloat16* Bhi = reinterpret_cast<__nv_bfloat16*>(sm + OFF_BHI);
    __nv_bfloat16* Blo = reinterpret_cast<__nv_bfloat16*>(sm + OFF_BLO);
    float* hbuf = reinterpret_cast<float*>(sm + OFF_HB);
    float* w5   = reinterpret_cast<float*>(sm + OFF_W5);
    float* xbuf = reinterpret_cast<float*>(sm + OFF_XB);   // alias A region
    float* pp   = reinterpret_cast<float*>(sm + OFF_PP);
    float* o1s  = reinterpret_cast<float*>(sm + OFF_O1);

    const int tid = threadIdx.x, lane = tid & 31, w = tid >> 5;
    const int nrf = B * 3;

    // ---- stage Wp hi/lo (full K) + small mats (once) ----
    #pragma unroll
    for (int t = 0; t < 8; t++) {
        int i = tid + t * THREADS;
        int n = i >> 6, c4 = i & 63;
        float4 v = reinterpret_cast<const float4*>(Wp)[i];
        uint2 hi, lo;
        split4(v, hi, lo);
        *reinterpret_cast<uint2*>(&Bhi[n * BSTRIDE + c4 * 4]) = hi;
        *reinterpret_cast<uint2*>(&Blo[n * BSTRIDE + c4 * 4]) = lo;
    }
    for (int i = tid; i < D * D; i += THREADS) {
        int jj = i >> 5, dd = i & 31;
        int o = jj * WSTRIDE + dd;
        w5[0 * D * WSTRIDE + o] = Wq [i];
        w5[1 * D * WSTRIDE + o] = Wk [i];
        w5[2 * D * WSTRIDE + o] = Wv [i];
        w5[3 * D * WSTRIDE + o] = Wo1[i];
        w5[4 * D * WSTRIDE + o] = Wo2[i];
    }
    const float bp_l  = bp [lane];
    const float g_l   = ln_g[lane];
    const float b_l   = ln_b[lane];
    const float bq_l  = bq [lane];
    const float bk_l  = bk [lane];
    const float bv_l  = bv [lane];
    const float bo1_l = bo1[lane];
    const float bo2_l = bo2[lane];

    // quarter slots: i = tid + t*256 (t<8): rf_l = i>>4 (0..127), c4 = i&15
    auto ldg_q = [&](int tile, int q, float4 (&buf)[8]) {
        #pragma unroll
        for (int t = 0; t < 8; t++) {
            int i = tid + t * THREADS;
            int rf_l = i >> 4, c4 = i & 15;
            int rf_g = tile * TILE_RF + rf_l;
            float4 v = make_float4(0.f, 0.f, 0.f, 0.f);
            if (rf_l < TILE_RF && rf_g < nrf) {
                int row = rf_g / 3, ft = rf_g - 3 * row;
                const float* src = (ft == 0) ? f1 : (ft == 1) ? f4 : fD;
                v = reinterpret_cast<const float4*>(src)[row * 64 + q * 16 + c4];
            }
            buf[t] = v;
        }
    };
    auto cvt_q = [&](float4 (&buf)[8]) {
        #pragma unroll
        for (int t = 0; t < 8; t++) {
            int i = tid + t * THREADS;
            int rf_l = i >> 4, c4 = i & 15;
            uint2 hi, lo;
            split4(buf[t], hi, lo);
            *reinterpret_cast<uint2*>(&Ahi[rf_l * ASTRIDE + c4 * 4]) = hi;
            *reinterpret_cast<uint2*>(&Alo[rf_l * ASTRIDE + c4 * 4]) = lo;
        }
    };

    float4 buf[8];
    int tile0 = blockIdx.x;
    if (tile0 < ntiles) ldg_q(tile0, 0, buf);
    __syncthreads();   // B + w5 staged

    for (int tile = tile0; tile < ntiles; tile += gridDim.x) {
        // ============ GEMM phase ============
        wmma::fragment<wmma::accumulator, 16, 16, 16, float> C[2];
        wmma::fill_fragment(C[0], 0.f);
        wmma::fill_fragment(C[1], 0.f);

        #pragma unroll
        for (int q = 0; q < 4; q++) {
            cvt_q(buf);
            if (q < 3) {
                ldg_q(tile, q + 1, buf);
            } else {
                int nt = tile + gridDim.x;
                if (nt < ntiles) ldg_q(nt, 0, buf);
            }
            __syncthreads();   // A quarter ready

            const __nv_bfloat16* Aw_h = Ahi + (w * 16) * ASTRIDE;
            const __nv_bfloat16* Aw_l = Alo + (w * 16) * ASTRIDE;
            const __nv_bfloat16* Bq_h = Bhi + q * KQ;
            const __nv_bfloat16* Bq_l = Blo + q * KQ;
            #pragma unroll
            for (int k = 0; k < KQ / 16; k++) {
                wmma::fragment<wmma::matrix_a, 16, 16, 16, __nv_bfloat16, wmma::row_major> ah, al;
                wmma::load_matrix_sync(ah, Aw_h + k * 16, ASTRIDE);
                wmma::load_matrix_sync(al, Aw_l + k * 16, ASTRIDE);
                #pragma unroll
                for (int n = 0; n < 2; n++) {
                    wmma::fragment<wmma::matrix_b, 16, 16, 16, __nv_bfloat16, wmma::col_major> bh, bl;
                    wmma::load_matrix_sync(bh, Bq_h + n * 16 * BSTRIDE + k * 16, BSTRIDE);
                    wmma::load_matrix_sync(bl, Bq_l + n * 16 * BSTRIDE + k * 16, BSTRIDE);
                    wmma::mma_sync(C[n], ah, bh, C[n]);
                    wmma::mma_sync(C[n], al, bh, C[n]);
                    wmma::mma_sync(C[n], ah, bl, C[n]);
                }
            }
            __syncthreads();   // A consumed (next cvt may overwrite)
        }

        // C -> hbuf (smem)
        wmma::store_matrix_sync(hbuf + (w * 16) * D,      C[0], D, wmma::mem_row_major);
        wmma::store_matrix_sync(hbuf + (w * 16) * D + 16, C[1], D, wmma::mem_row_major);
        __syncthreads();   // hbuf ready; A region free for epi scratch

        // ============ epilogue phase ============
        const int row0 = tile * TILE_ROWS;
        const int rows_here = (B - row0 < TILE_ROWS) ? (B - row0) : TILE_ROWS;

        for (int r = w; r < rows_here; r += 8) {
            // ---- bias + relu + LN ----
            #pragma unroll
            for (int s = 0; s < 3; s++) {
                float h = hbuf[(r * 3 + s) * D + lane] + bp_l;
                h = fmaxf(h, 0.f);
                float mu  = wsum(h) * (1.f / 32.f);
                float dv  = h - mu;
                float var = wsum(dv * dv) * (1.f / 32.f);
                xbuf[(w * 3 + s) * D + lane] = g_l * dv * rsqrtf(var + LN_EPS) + b_l;
            }
            __syncwarp();

            // ---- QKV ----
            float qkvr[3][3];
            float bias3[3] = { bq_l, bk_l, bv_l };
            #pragma unroll
            for (int mat = 0; mat < 3; mat++) {
                const ulonglong2* wrow = reinterpret_cast<const ulonglong2*>(
                    w5 + mat * D * WSTRIDE + lane * WSTRIDE);
                u64 a0[3] = {0ull,0ull,0ull}, a1[3] = {0ull,0ull,0ull};
                #pragma unroll
                for (int c = 0; c < 8; c++) {
                    ulonglong2 wv = wrow[c];
                    #pragma unroll
                    for (int ss = 0; ss < 3; ss++) {
                        ulonglong2 xv = reinterpret_cast<const ulonglong2*>(
                            xbuf + (w * 3 + ss) * D)[c];
                        ffma2(a0[ss], wv.x, xv.x);
                        ffma2(a1[ss], wv.y, xv.y);
                    }
                }
                #pragma unroll
                for (int ss = 0; ss < 3; ss++)
                    qkvr[mat][ss] = hsum2(a0[ss], a1[ss]) + bias3[mat];
            }

            // ---- attention + softmax + pool ----
            const float scale = 0.17677669529663687f;   // 1/sqrt(32)
            float att[3][3];
            #pragma unroll
            for (int ss = 0; ss < 3; ss++)
                #pragma unroll
                for (int tt = 0; tt < 3; tt++)
                    att[ss][tt] = wsum(qkvr[0][ss] * qkvr[1][tt]) * scale;

            float pool = 0.f;
            #pragma unroll
            for (int ss = 0; ss < 3; ss++) {
                float m  = fmaxf(att[ss][0], fmaxf(att[ss][1], att[ss][2]));
                float e0 = __expf(att[ss][0] - m);
                float e1 = __expf(att[ss][1] - m);
                float e2 = __expf(att[ss][2] - m);
                float ri = 1.f / (e0 + e1 + e2);
                pool += (e0 * qkvr[2][0] + e1 * qkvr[2][1] + e2 * qkvr[2][2]) * ri;
            }
            pool *= (1.f / 3.f);
            pp[w * D + lane] = pool;
            __syncwarp();

            // ---- O1 ----
            {
                const ulonglong2* pv = reinterpret_cast<const ulonglong2*>(pp + w * D);
                const ulonglong2* w1 = reinterpret_cast<const ulonglong2*>(
                    w5 + 3 * D * WSTRIDE + lane * WSTRIDE);
                u64 a0 = 0ull, a1 = 0ull;
                #pragma unroll
                for (int c = 0; c < 8; c++) {
                    ulonglong2 pvv = pv[c], wv = w1[c];
                    ffma2(a0, wv.x, pvv.x);
                    ffma2(a1, wv.y, pvv.y);
                }
                o1s[w * D + lane] = fmaxf(hsum2(a0, a1) + bo1_l, 0.f);
            }
            __syncwarp();

            // ---- O2 + residual + store ----
            {
                const ulonglong2* ov = reinterpret_cast<const ulonglong2*>(o1s + w * D);
                const ulonglong2* w2 = reinterpret_cast<const ulonglong2*>(
                    w5 + 4 * D * WSTRIDE + lane * WSTRIDE);
                u64 a0 = 0ull, a1 = 0ull;
                #pragma unroll
                for (int c = 0; c < 8; c++) {
                    ulonglong2 ovv = ov[c], wv = w2[c];
                    ffma2(a0, wv.x, ovv.x);
                    ffma2(a1, wv.y, ovv.y);
                }
                out[(size_t)(row0 + r) * D + lane] = hsum2(a0, a1) + bo2_l + pool;
            }
            __syncwarp();
        }
        __syncthreads();   // epi done (xbuf in A region) before next tile's cvt
    }
}

// ================= launch =================
extern "C" void kernel_launch(void* const* d_in, const int* in_sizes, int n_in,
                              void* d_out, int out_size)
{
    const float* f1   = (const float*)d_in[0];
    const float* f4   = (const float*)d_in[1];
    const float* fD   = (const float*)d_in[2];
    const float* Wp   = (const float*)d_in[3];
    const float* bp   = (const float*)d_in[4];
    const float* ln_g = (const float*)d_in[5];
    const float* ln_b = (const float*)d_in[6];
    const float* Wq   = (const float*)d_in[7];
    const float* bq   = (const float*)d_in[8];
    const float* Wk   = (const float*)d_in[9];
    const float* bk   = (const float*)d_in[10];
    const float* Wv   = (const float*)d_in[11];
    const float* bv   = (const float*)d_in[12];
    const float* Wo1  = (const float*)d_in[13];
    const float* bo1  = (const float*)d_in[14];
    const float* Wo2  = (const float*)d_in[15];
    const float* bo2  = (const float*)d_in[16];

    const int B = in_sizes[0] / IN_DIM;
    const int ntiles = (B + TILE_ROWS - 1) / TILE_ROWS;

    cudaFuncSetAttribute(fused_kernel, cudaFuncAttributeMaxDynamicSharedMemorySize, SMEM_SZ);

    int grid = ntiles < 304 ? ntiles : 304;   // 2 blocks x 152 SMs
    fused_kernel<<<grid, THREADS, SMEM_SZ>>>(
        f1, f4, fD, Wp, bp, ln_g, ln_b, Wq, bq, Wk, bk, Wv, bv,
        Wo1, bo1, Wo2, bo2, (float*)d_out, B, ntiles);
}

// round 14
// speedup vs baseline: 2.1542x; 1.0492x over previous
#include <cuda_runtime.h>
#include <cuda_bf16.h>
#include <mma.h>
#include <cstdint>

using namespace nvcuda;
using u64 = unsigned long long;
#define FULL_MASK 0xFFFFFFFFu

constexpr int IN_DIM = 256;
constexpr int D = 32;
constexpr float LN_EPS = 1e-5f;

constexpr int TILE_ROWS = 42;          // rows per block tile
constexpr int TILE_RF   = 126;         // 42*3 rf (2 pad rows up to 128)
constexpr int KQ        = 64;          // k-quarter
constexpr int ASTRIDE   = 72;          // bf16 elems per A row (144 B)
constexpr int BSTRIDE   = 260;         // bf16 elems per B row (full K)
constexpr int WSTRIDE   = 36;
constexpr int THREADS   = 256;

// ---- smem layout (bytes) ----
constexpr int OFF_AHI = 0;                                   // 18432
constexpr int OFF_ALO = OFF_AHI + 128 * ASTRIDE * 2;         // 18432
constexpr int OFF_BHI = OFF_ALO + 128 * ASTRIDE * 2;         // 16640
constexpr int OFF_BLO = OFF_BHI + D * BSTRIDE * 2;           // 16640
constexpr int OFF_HB  = OFF_BLO + D * BSTRIDE * 2;           // 16384
constexpr int OFF_W5  = OFF_HB + 128 * D * 4;                // 23040
constexpr int OFF_EPI = OFF_W5 + 5 * D * WSTRIDE * 4;        // dedicated epi scratch
constexpr int OFF_XB  = OFF_EPI;                             // 8*3*32*4 = 3072
constexpr int OFF_PP  = OFF_EPI + 3072;                      // 8*32*4   = 1024
constexpr int OFF_O1  = OFF_EPI + 4096;                      // 8*32*4   = 1024
constexpr int SMEM_SZ = OFF_EPI + 5120;                      // 114688 -> 2 blocks/SM

__device__ __forceinline__ void split4(float4 v, uint2& hi, uint2& lo) {
    __nv_bfloat162 h01 = __floats2bfloat162_rn(v.x, v.y);
    __nv_bfloat162 h23 = __floats2bfloat162_rn(v.z, v.w);
    float lx = v.x - __low2float(h01),  ly = v.y - __high2float(h01);
    float lz = v.z - __low2float(h23),  lw = v.w - __high2float(h23);
    __nv_bfloat162 l01 = __floats2bfloat162_rn(lx, ly);
    __nv_bfloat162 l23 = __floats2bfloat162_rn(lz, lw);
    hi.x = *reinterpret_cast<uint32_t*>(&h01);
    hi.y = *reinterpret_cast<uint32_t*>(&h23);
    lo.x = *reinterpret_cast<uint32_t*>(&l01);
    lo.y = *reinterpret_cast<uint32_t*>(&l23);
}
__device__ __forceinline__ void ffma2(u64& d, u64 a, u64 b) {
    asm("fma.rn.f32x2 %0, %1, %2, %0;" : "+l"(d) : "l"(a), "l"(b));
}
__device__ __forceinline__ float hsum2(u64 a, u64 b) {
    return __uint_as_float((unsigned)a) + __uint_as_float((unsigned)(a >> 32))
         + __uint_as_float((unsigned)b) + __uint_as_float((unsigned)(b >> 32));
}
__device__ __forceinline__ float wsum(float v) {
    v += __shfl_xor_sync(FULL_MASK, v, 16);
    v += __shfl_xor_sync(FULL_MASK, v, 8);
    v += __shfl_xor_sync(FULL_MASK, v, 4);
    v += __shfl_xor_sync(FULL_MASK, v, 2);
    v += __shfl_xor_sync(FULL_MASK, v, 1);
    return v;
}

// ================= fused kernel =================
__global__ __launch_bounds__(THREADS, 2)
void fused_kernel(const float* __restrict__ f1, const float* __restrict__ f4,
                  const float* __restrict__ fD,
                  const float* __restrict__ Wp,  const float* __restrict__ bp,
                  const float* __restrict__ ln_g, const float* __restrict__ ln_b,
                  const float* __restrict__ Wq,  const float* __restrict__ bq,
                  const float* __restrict__ Wk,  const float* __restrict__ bk,
                  const float* __restrict__ Wv,  const float* __restrict__ bv,
                  const float* __restrict__ Wo1, const float* __restrict__ bo1,
                  const float* __restrict__ Wo2, const float* __restrict__ bo2,
                  float* __restrict__ out, int B, int ntiles)
{
    extern __shared__ char sm[];
    __nv_bfloat16* Ahi = reinterpret_cast<__nv_bfloat16*>(sm + OFF_AHI);
    __nv_bfloat16* Alo = reinterpret_cast<__nv_bfloat16*>(sm + OFF_ALO);
    __nv_bfloat16* Bhi = reinterpret_cast<__nv_bfloat16*>(sm + OFF_BHI);
    __nv_bfloat16* Blo = reinterpret_cast<__nv_bfloat16*>(sm + OFF_BLO);
    float* hbuf = reinterpret_cast<float*>(sm + OFF_HB);
    float* w5   = reinterpret_cast<float*>(sm + OFF_W5);
    float* xbuf = reinterpret_cast<float*>(sm + OFF_XB);
    float* pp   = reinterpret_cast<float*>(sm + OFF_PP);
    float* o1s  = reinterpret_cast<float*>(sm + OFF_O1);

    const int tid = threadIdx.x, lane = tid & 31, w = tid >> 5;
    const int nrf = B * 3;

    // ---- stage Wp hi/lo (full K) + small mats (once) ----
    #pragma unroll
    for (int t = 0; t < 8; t++) {
        int i = tid + t * THREADS;
        int n = i >> 6, c4 = i & 63;
        float4 v = reinterpret_cast<const float4*>(Wp)[i];
        uint2 hi, lo;
        split4(v, hi, lo);
        *reinterpret_cast<uint2*>(&Bhi[n * BSTRIDE + c4 * 4]) = hi;
        *reinterpret_cast<uint2*>(&Blo[n * BSTRIDE + c4 * 4]) = lo;
    }
    for (int i = tid; i < D * D; i += THREADS) {
        int jj = i >> 5, dd = i & 31;
        int o = jj * WSTRIDE + dd;
        w5[0 * D * WSTRIDE + o] = Wq [i];
        w5[1 * D * WSTRIDE + o] = Wk [i];
        w5[2 * D * WSTRIDE + o] = Wv [i];
        w5[3 * D * WSTRIDE + o] = Wo1[i];
        w5[4 * D * WSTRIDE + o] = Wo2[i];
    }
    const float bp_l  = bp [lane];
    const float g_l   = ln_g[lane];
    const float b_l   = ln_b[lane];
    const float bq_l  = bq [lane];
    const float bk_l  = bk [lane];
    const float bv_l  = bv [lane];
    const float bo1_l = bo1[lane];
    const float bo2_l = bo2[lane];

    auto ldg_q = [&](int tile, int q, float4 (&buf)[8]) {
        #pragma unroll
        for (int t = 0; t < 8; t++) {
            int i = tid + t * THREADS;
            int rf_l = i >> 4, c4 = i & 15;
            int rf_g = tile * TILE_RF + rf_l;
            float4 v = make_float4(0.f, 0.f, 0.f, 0.f);
            if (rf_l < TILE_RF && rf_g < nrf) {
                int row = rf_g / 3, ft = rf_g - 3 * row;
                const float* src = (ft == 0) ? f1 : (ft == 1) ? f4 : fD;
                v = reinterpret_cast<const float4*>(src)[row * 64 + q * 16 + c4];
            }
            buf[t] = v;
        }
    };
    auto cvt_q = [&](float4 (&buf)[8]) {
        #pragma unroll
        for (int t = 0; t < 8; t++) {
            int i = tid + t * THREADS;
            int rf_l = i >> 4, c4 = i & 15;
            uint2 hi, lo;
            split4(buf[t], hi, lo);
            *reinterpret_cast<uint2*>(&Ahi[rf_l * ASTRIDE + c4 * 4]) = hi;
            *reinterpret_cast<uint2*>(&Alo[rf_l * ASTRIDE + c4 * 4]) = lo;
        }
    };

    float4 buf[8];
    int tile0 = blockIdx.x;
    if (tile0 < ntiles) ldg_q(tile0, 0, buf);
    __syncthreads();   // B + w5 staged

    for (int tile = tile0; tile < ntiles; tile += gridDim.x) {
        // ============ GEMM phase ============
        wmma::fragment<wmma::accumulator, 16, 16, 16, float> C[2];
        wmma::fill_fragment(C[0], 0.f);
        wmma::fill_fragment(C[1], 0.f);

        #pragma unroll
        for (int q = 0; q < 4; q++) {
            cvt_q(buf);
            if (q < 3) {
                ldg_q(tile, q + 1, buf);
            } else {
                int nt = tile + gridDim.x;
                if (nt < ntiles) ldg_q(nt, 0, buf);
            }
            __syncthreads();   // A quarter ready (also orders prev-tile epi before C-store below)

            const __nv_bfloat16* Aw_h = Ahi + (w * 16) * ASTRIDE;
            const __nv_bfloat16* Aw_l = Alo + (w * 16) * ASTRIDE;
            const __nv_bfloat16* Bq_h = Bhi + q * KQ;
            const __nv_bfloat16* Bq_l = Blo + q * KQ;
            #pragma unroll
            for (int k = 0; k < KQ / 16; k++) {
                wmma::fragment<wmma::matrix_a, 16, 16, 16, __nv_bfloat16, wmma::row_major> ah, al;
                wmma::load_matrix_sync(ah, Aw_h + k * 16, ASTRIDE);
                wmma::load_matrix_sync(al, Aw_l + k * 16, ASTRIDE);
                #pragma unroll
                for (int n = 0; n < 2; n++) {
                    wmma::fragment<wmma::matrix_b, 16, 16, 16, __nv_bfloat16, wmma::col_major> bh, bl;
                    wmma::load_matrix_sync(bh, Bq_h + n * 16 * BSTRIDE + k * 16, BSTRIDE);
                    wmma::load_matrix_sync(bl, Bq_l + n * 16 * BSTRIDE + k * 16, BSTRIDE);
                    wmma::mma_sync(C[n], ah, bh, C[n]);
                    wmma::mma_sync(C[n], al, bh, C[n]);
                    wmma::mma_sync(C[n], ah, bl, C[n]);
                }
            }
            __syncthreads();   // A consumed (next cvt may overwrite)
        }

        // C -> hbuf (smem)
        wmma::store_matrix_sync(hbuf + (w * 16) * D,      C[0], D, wmma::mem_row_major);
        wmma::store_matrix_sync(hbuf + (w * 16) * D + 16, C[1], D, wmma::mem_row_major);
        __syncthreads();   // hbuf ready

        // ============ epilogue phase (warp-autonomous; no end barrier) ============
        const int row0 = tile * TILE_ROWS;
        const int rows_here = (B - row0 < TILE_ROWS) ? (B - row0) : TILE_ROWS;

        for (int r = w; r < rows_here; r += 8) {
            // ---- bias + relu + LN (parallel sum / sumsq) ----
            #pragma unroll
            for (int s = 0; s < 3; s++) {
                float h = hbuf[(r * 3 + s) * D + lane] + bp_l;
                h = fmaxf(h, 0.f);
                float s1 = wsum(h);
                float s2 = wsum(h * h);          // independent of s1 -> chains overlap
                float mu  = s1 * (1.f / 32.f);
                float var = fmaxf(s2 * (1.f / 32.f) - mu * mu, 0.f);
                xbuf[(w * 3 + s) * D + lane] =
                    g_l * (h - mu) * rsqrtf(var + LN_EPS) + b_l;
            }
            __syncwarp();

            // ---- QKV ----
            float qkvr[3][3];
            float bias3[3] = { bq_l, bk_l, bv_l };
            #pragma unroll
            for (int mat = 0; mat < 3; mat++) {
                const ulonglong2* wrow = reinterpret_cast<const ulonglong2*>(
                    w5 + mat * D * WSTRIDE + lane * WSTRIDE);
                u64 a0[3] = {0ull,0ull,0ull}, a1[3] = {0ull,0ull,0ull};
                #pragma unroll
                for (int c = 0; c < 8; c++) {
                    ulonglong2 wv = wrow[c];
                    #pragma unroll
                    for (int ss = 0; ss < 3; ss++) {
                        ulonglong2 xv = reinterpret_cast<const ulonglong2*>(
                            xbuf + (w * 3 + ss) * D)[c];
                        ffma2(a0[ss], wv.x, xv.x);
                        ffma2(a1[ss], wv.y, xv.y);
                    }
                }
                #pragma unroll
                for (int ss = 0; ss < 3; ss++)
                    qkvr[mat][ss] = hsum2(a0[ss], a1[ss]) + bias3[mat];
            }

            // ---- attention + softmax + pool ----
            const float scale = 0.17677669529663687f;   // 1/sqrt(32)
            float att[3][3];
            #pragma unroll
            for (int ss = 0; ss < 3; ss++)
                #pragma unroll
                for (int tt = 0; tt < 3; tt++)
                    att[ss][tt] = wsum(qkvr[0][ss] * qkvr[1][tt]) * scale;

            float pool = 0.f;
            #pragma unroll
            for (int ss = 0; ss < 3; ss++) {
                float m  = fmaxf(att[ss][0], fmaxf(att[ss][1], att[ss][2]));
                float e0 = __expf(att[ss][0] - m);
                float e1 = __expf(att[ss][1] - m);
                float e2 = __expf(att[ss][2] - m);
                float ri = 1.f / (e0 + e1 + e2);
                pool += (e0 * qkvr[2][0] + e1 * qkvr[2][1] + e2 * qkvr[2][2]) * ri;
            }
            pool *= (1.f / 3.f);
            pp[w * D + lane] = pool;
            __syncwarp();

            // ---- O1 ----
            {
                const ulonglong2* pv = reinterpret_cast<const ulonglong2*>(pp + w * D);
                const ulonglong2* w1 = reinterpret_cast<const ulonglong2*>(
                    w5 + 3 * D * WSTRIDE + lane * WSTRIDE);
                u64 a0 = 0ull, a1 = 0ull;
                #pragma unroll
                for (int c = 0; c < 8; c++) {
                    ulonglong2 pvv = pv[c], wv = w1[c];
                    ffma2(a0, wv.x, pvv.x);
                    ffma2(a1, wv.y, pvv.y);
                }
                o1s[w * D + lane] = fmaxf(hsum2(a0, a1) + bo1_l, 0.f);
            }
            __syncwarp();

            // ---- O2 + residual + store ----
            {
                const ulonglong2* ov = reinterpret_cast<const ulonglong2*>(o1s + w * D);
                const ulonglong2* w2 = reinterpret_cast<const ulonglong2*>(
                    w5 + 4 * D * WSTRIDE + lane * WSTRIDE);
                u64 a0 = 0ull, a1 = 0ull;
                #pragma unroll
                for (int c = 0; c < 8; c++) {
                    ulonglong2 ovv = ov[c], wv = w2[c];
                    ffma2(a0, wv.x, ovv.x);
                    ffma2(a1, wv.y, ovv.y);
                }
                out[(size_t)(row0 + r) * D + lane] = hsum2(a0, a1) + bo2_l + pool;
            }
            __syncwarp();
        }
        // NO end-of-tile barrier: epi scratch is dedicated; the first GEMM
        // barrier of the next tile provides the hbuf/A ordering.
    }
}

// ================= launch =================
extern "C" void kernel_launch(void* const* d_in, const int* in_sizes, int n_in,
                              void* d_out, int out_size)
{
    const float* f1   = (const float*)d_in[0];
    const float* f4   = (const float*)d_in[1];
    const float* fD   = (const float*)d_in[2];
    const float* Wp   = (const float*)d_in[3];
    const float* bp   = (const float*)d_in[4];
    const float* ln_g = (const float*)d_in[5];
    const float* ln_b = (const float*)d_in[6];
    const float* Wq   = (const float*)d_in[7];
    const float* bq   = (const float*)d_in[8];
    const float* Wk   = (const float*)d_in[9];
    const float* bk   = (const float*)d_in[10];
    const float* Wv   = (const float*)d_in[11];
    const float* bv   = (const float*)d_in[12];
    const float* Wo1  = (const float*)d_in[13];
    const float* bo1  = (const float*)d_in[14];
    const float* Wo2  = (const float*)d_in[15];
    const float* bo2  = (const float*)d_in[16];

    const int B = in_sizes[0] / IN_DIM;
    const int ntiles = (B + TILE_ROWS - 1) / TILE_ROWS;

    cudaFuncSetAttribute(fused_kernel, cudaFuncAttributeMaxDynamicSharedMemorySize, SMEM_SZ);

    int grid = ntiles < 304 ? ntiles : 304;   // 2 blocks x 152 SMs
    fused_kernel<<<grid, THREADS, SMEM_SZ>>>(
        f1, f4, fD, Wp, bp, ln_g, ln_b, Wq, bq, Wk, bk, Wv, bv,
        Wo1, bo1, Wo2, bo2, (float*)d_out, B, ntiles);
}